// round 16
// baseline (speedup 1.0000x reference)
#include <cuda_runtime.h>
#include <cuda_fp16.h>
#include <cstdint>

// Problem constants
#define TT 8192
#define HH 2048
#define EE 8

// GEMM config
#define BM 128
#define BN 256
#define BK 64
#define NCH (HH / BK)          // 32 k-chunks
#define STG 4
#define A_BYTES 16384          // 128 rows x 128B
#define B_BYTES 32768          // 256 rows x 128B
#define STAGE_BYTES (A_BYTES + B_BYTES)   // 48KB
#define SMEM_NEED (STG * STAGE_BYTES)     // 196608, occupancy 1
#define BSCALE 4096.0f
#define INV_BSCALE (1.0f / 4096.0f)

// ---------------- static scratch ----------------
__device__ int    g_counts[EE];
__device__ int    g_list[EE][TT];
__device__ float  g_gate[2 * TT];
__device__ __half g_Ah[(size_t)TT * HH];
__device__ __half g_Bh[(size_t)EE * HH * HH];   // [e][n][k], scaled by 4096

// ---------------- helpers ----------------
__device__ __forceinline__ uint32_t smem_u32(const void* p) {
    uint32_t a;
    asm("{ .reg .u64 t; cvta.to.shared.u64 t, %1; cvt.u32.u64 %0, t; }" : "=r"(a) : "l"(p));
    return a;
}
__device__ __forceinline__ uint32_t h2u(__half2 h) { return *(uint32_t*)&h; }

#define CPA(dst, src) \
    asm volatile("cp.async.cg.shared.global [%0], [%1], 16;" :: "r"(dst), "l"(src))
#define CP_COMMIT() asm volatile("cp.async.commit_group;" ::: "memory")
#define CP_WAIT2()  asm volatile("cp.async.wait_group 2;" ::: "memory")

#define LDSM4(r, addr) \
    asm volatile("ldmatrix.sync.aligned.m8n8.x4.shared.b16 {%0,%1,%2,%3}, [%4];" \
                 : "=r"((r)[0]), "=r"((r)[1]), "=r"((r)[2]), "=r"((r)[3]) : "r"(addr))

#define MMA(c, a, b) \
    asm volatile("mma.sync.aligned.m16n8k16.row.col.f32.f16.f16.f32 " \
                 "{%0,%1,%2,%3},{%4,%5,%6,%7},{%8,%9},{%0,%1,%2,%3};" \
                 : "+f"((c)[0]), "+f"((c)[1]), "+f"((c)[2]), "+f"((c)[3]) \
                 : "r"((a)[0]), "r"((a)[1]), "r"((a)[2]), "r"((a)[3]), \
                   "r"((b)[0]), "r"((b)[1]))

#define REDADD(ptr, val) \
    asm volatile("red.global.add.f32 [%0], %1;" :: "l"(ptr), "f"(val) : "memory")

// ---------------- kernel 0: zero output + reset counters ----------------
__global__ void k_zero(float* __restrict__ out) {
    if (blockIdx.x == 0 && threadIdx.x < EE) g_counts[threadIdx.x] = 0;
    size_t i = (size_t)blockIdx.x * blockDim.x + threadIdx.x;   // float4 index
    ((float4*)out)[i] = make_float4(0.f, 0.f, 0.f, 0.f);
}

// ---------------- kernel 1: We [e][k][n] -> Bh fp16 [e][n][k], scaled ----------------
__global__ __launch_bounds__(512, 1)
void k_prep_B(const float* __restrict__ We) {
    const int e = blockIdx.z;
    const int k0 = blockIdx.y * 128 + (threadIdx.x >> 8) * 64;
    const int n0 = blockIdx.x * 64;
    __shared__ float t[2][64][65];
    float (*tt)[65] = t[threadIdx.x >> 8];
    const int tid = threadIdx.x & 255;
#pragma unroll
    for (int q = 0; q < 16; ++q) {
        int lin = q * 256 + tid;
        int kr = lin >> 6, nc = lin & 63;
        tt[kr][nc] = We[((size_t)e * HH + (k0 + kr)) * HH + n0 + nc];
    }
    __syncthreads();
#pragma unroll
    for (int q = 0; q < 8; ++q) {
        int lin = q * 256 + tid;
        int nr = lin >> 5, kc = (lin & 31) * 2;
        float a = tt[kc][nr] * BSCALE;
        float b = tt[kc + 1][nr] * BSCALE;
        __half2 h = __floats2half2_rn(a, b);
        size_t off = ((size_t)e * HH + (n0 + nr)) * HH + k0 + kc;
        *(uint32_t*)(g_Bh + off) = h2u(h);
    }
}

// ---------------- kernel 2: gating + x->fp16 conversion (fused) ----------------
__global__ void k_gate(const float* __restrict__ x,
                       const float* __restrict__ Wg,
                       const float* __restrict__ bg) {
    int gw = (blockIdx.x * blockDim.x + threadIdx.x) >> 5;
    int lane = threadIdx.x & 31;
    if (gw >= TT) return;
    const float* xr = x + (size_t)gw * HH;
    __half* ar = g_Ah + (size_t)gw * HH;

    float acc[EE];
#pragma unroll
    for (int e = 0; e < EE; ++e) acc[e] = 0.0f;
    for (int h = lane; h < HH; h += 32) {
        float xv = xr[h];
        ar[h] = __float2half_rn(xv);           // fused prep_x (coalesced 64B/warp)
        const float4* w4 = (const float4*)(Wg + (size_t)h * EE);
        float4 w0 = w4[0], w1 = w4[1];
        acc[0] += xv * w0.x; acc[1] += xv * w0.y;
        acc[2] += xv * w0.z; acc[3] += xv * w0.w;
        acc[4] += xv * w1.x; acc[5] += xv * w1.y;
        acc[6] += xv * w1.z; acc[7] += xv * w1.w;
    }
#pragma unroll
    for (int o = 16; o; o >>= 1)
#pragma unroll
        for (int e = 0; e < EE; ++e)
            acc[e] += __shfl_xor_sync(0xffffffffu, acc[e], o);

    if (lane == 0) {
        float m = -1e30f;
#pragma unroll
        for (int e = 0; e < EE; ++e) { acc[e] += bg[e]; m = fmaxf(m, acc[e]); }
        float sc[EE], s = 0.0f;
#pragma unroll
        for (int e = 0; e < EE; ++e) { sc[e] = expf(acc[e] - m); s += sc[e]; }
        float inv = 1.0f / s;
#pragma unroll
        for (int e = 0; e < EE; ++e) sc[e] *= inv;
        int e0 = 0;
#pragma unroll
        for (int e = 1; e < EE; ++e) if (sc[e] > sc[e0]) e0 = e;
        int e1 = (e0 == 0) ? 1 : 0;
#pragma unroll
        for (int e = 0; e < EE; ++e) if (e != e0 && sc[e] > sc[e1]) e1 = e;
        int t = gw;
        g_gate[2 * t + 0] = sc[e0];
        g_gate[2 * t + 1] = sc[e1];
        int p0 = atomicAdd(&g_counts[e0], 1);
        g_list[e0][p0] = 2 * t + 0;
        int p1 = atomicAdd(&g_counts[e1], 1);
        g_list[e1][p1] = 2 * t + 1;
    }
}

// ---------------- kernel 3: fp16 grouped GEMM, 128x256 tile, 64x64 warp tiles ----------------
__global__ __launch_bounds__(256, 1)
void k_gemm_mma(const float* __restrict__ be, float* __restrict__ out) {
    const int e = blockIdx.z;
    const int count = g_counts[e];
    const int row0 = blockIdx.y * BM;
    if (row0 >= count) return;
    const int n0 = blockIdx.x * BN;

    extern __shared__ char smem_raw[];
    const uint32_t sb = smem_u32(smem_raw);
    const int tid = threadIdx.x;
    const int w = tid >> 5, l = tid & 31;

    // cp.async assignments: loader row rA (0..31), 16B chunk ch (0..7)
    const int rA = tid >> 3;
    const int ch = tid & 7;
    const __half* srcA[4];
    uint32_t dstoffA[4];
#pragma unroll
    for (int q = 0; q < 4; ++q) {
        int r = rA + 32 * q;
        int gr = row0 + r;
        int cl = (gr < count) ? gr : (count - 1);
        int slot = g_list[e][cl];
        srcA[q] = g_Ah + (size_t)(slot >> 1) * HH + ch * 8;
        dstoffA[q] = (uint32_t)r * 128u + (uint32_t)((ch ^ (rA & 7)) << 4);
    }
    const __half* srcB0 = g_Bh + ((size_t)e * HH + n0 + rA) * HH + ch * 8;
    const uint32_t dstoffB0 = (uint32_t)rA * 128u + (uint32_t)((ch ^ (rA & 7)) << 4);

    auto issue = [&](int s, int c) {
        const uint32_t base = sb + s * STAGE_BYTES;
        const int ke = c * BK;
#pragma unroll
        for (int q = 0; q < 4; ++q) CPA(base + dstoffA[q], srcA[q] + ke);
        const uint32_t bbase = base + A_BYTES + dstoffB0;
        const __half* bs = srcB0 + ke;
#pragma unroll
        for (int q = 0; q < 8; ++q)
            CPA(bbase + (uint32_t)q * (32u * 128u), bs + (size_t)q * 32 * HH);
    };

    // prologue: 3 stages in flight
    issue(0, 0); CP_COMMIT();
    issue(1, 1); CP_COMMIT();
    issue(2, 2); CP_COMMIT();

    // per-warp tile: 64 rows x 64 cols  (warp grid 2m x 4n)
    const int m_base = (w & 1) * 64;
    const int n_base = (w >> 1) * 64;

    uint32_t rowA[4], rowB[4], xoA[4], xoB[4];
#pragma unroll
    for (int i = 0; i < 4; ++i) rowA[i] = (uint32_t)(m_base + 16 * i + (l & 15)) * 128u;
#pragma unroll
    for (int j2 = 0; j2 < 4; ++j2)
        rowB[j2] = (uint32_t)(n_base + 16 * j2 + (l & 7) + ((l >> 4) << 3)) * 128u;
#pragma unroll
    for (int ks = 0; ks < 4; ++ks) {
        xoA[ks] = (uint32_t)(((ks * 2 + (l >> 4)) ^ (l & 7)) << 4);
        xoB[ks] = (uint32_t)(((ks * 2 + ((l >> 3) & 1)) ^ (l & 7)) << 4);
    }

    float acc[4][8][4];
#pragma unroll
    for (int i = 0; i < 4; ++i)
#pragma unroll
        for (int j = 0; j < 8; ++j)
#pragma unroll
            for (int q = 0; q < 4; ++q) acc[i][j][q] = 0.0f;

    uint32_t fa[4][4], fb[4][4];

    for (int c = 0; c < NCH; ++c) {
        CP_WAIT2();
        __syncthreads();
        // stage (c+3)%4 was consumed in iteration c-1 -> safe to refill
        if (c + 3 < NCH) issue((c + 3) % STG, c + 3);
        CP_COMMIT();

        const uint32_t Ah = sb + (c % STG) * STAGE_BYTES;
        const uint32_t Bh = Ah + A_BYTES;

#pragma unroll
        for (int ks = 0; ks < 4; ++ks) {
#pragma unroll
            for (int i = 0; i < 4; ++i) LDSM4(fa[i], Ah + rowA[i] + xoA[ks]);
#pragma unroll
            for (int j2 = 0; j2 < 4; ++j2) LDSM4(fb[j2], Bh + rowB[j2] + xoB[ks]);
#pragma unroll
            for (int i = 0; i < 4; ++i) {
#pragma unroll
                for (int j = 0; j < 8; ++j) {
                    MMA(acc[i][j], fa[i], (&fb[j >> 1][(j & 1) * 2]));
                }
            }
        }
    }

    // epilogue: out[token] += gate * (acc/BSCALE + be)   (exactly 2 adds/elem -> deterministic)
    float2 bias[8];
#pragma unroll
    for (int j = 0; j < 8; ++j) {
        int col = n_base + 8 * j + 2 * (l & 3);
        bias[j] = *(const float2*)(be + (size_t)e * HH + n0 + col);
    }
#pragma unroll
    for (int i = 0; i < 4; ++i) {
#pragma unroll
        for (int half = 0; half < 2; ++half) {
            int r = m_base + 16 * i + (l >> 2) + 8 * half;
            int gr = row0 + r;
            if (gr < count) {
                int slot = g_list[e][gr];
                float gate = g_gate[slot];
                float gs = gate * INV_BSCALE;
                float* yr = out + (size_t)(slot >> 1) * HH + n0;
#pragma unroll
                for (int j = 0; j < 8; ++j) {
                    int col = n_base + 8 * j + 2 * (l & 3);
                    float vx = gs * acc[i][j][half * 2 + 0] + gate * bias[j].x;
                    float vy = gs * acc[i][j][half * 2 + 1] + gate * bias[j].y;
                    REDADD(yr + col, vx);
                    REDADD(yr + col + 1, vy);
                }
            }
        }
    }
}

// ---------------- launch ----------------
extern "C" void kernel_launch(void* const* d_in, const int* in_sizes, int n_in,
                              void* d_out, int out_size) {
    const float* x  = (const float*)d_in[0];
    const float* Wg = (const float*)d_in[1];
    const float* bg = (const float*)d_in[2];
    const float* We = (const float*)d_in[3];
    const float* be = (const float*)d_in[4];
    float* out = (float*)d_out;

    cudaFuncSetAttribute(k_gemm_mma, cudaFuncAttributeMaxDynamicSharedMemorySize, SMEM_NEED);

    k_zero<<<(TT * (HH / 4)) / 256, 256>>>(out);
    k_prep_B<<<dim3(HH / 64, HH / 128, EE), 512>>>(We);
    k_gate<<<TT / 8, 256>>>(x, Wg, bg);
    k_gemm_mma<<<dim3(HH / BN, TT / BM, EE), 256, SMEM_NEED>>>(be, out);
}